// round 14
// baseline (speedup 1.0000x reference)
#include <cuda_runtime.h>
#include <cuda_fp16.h>
#include <mma.h>
#include <math.h>
#include <stdint.h>

#define B_  64
#define T_  512
#define IN_ 1024
#define H_  1024
#define L_  5
#define NC   128
#define TPB  256
#define NGRP 2
#define CPG  64
#define BPG  32
typedef unsigned long long ull;
using namespace nvcuda;

// smem: 8 warp-private state regions [64 rows][136 halves], then partials
#define WP    136
#define WREG  (64 * WP)                        // 8704 halves per warp region
#define ST_H  (8 * WREG)                       // 69632 halves
#define PRP   36
#define SMEM_BYTES (ST_H * 2 + 8 * 32 * PRP * 4)   // 139264 + 36864 = 176128

__device__ float  g_xw[(size_t)B_ * T_ * 2 * H_];
__device__ __half g_w16[2][2][(size_t)L_ * H_ * H_];   // recurrent W [gate][hi/lo]
__device__ __half g_s16[2][2][B_ * H_];                // state [buf][hi/lo]
__device__ __half g_x16[2][(size_t)B_ * T_ * IN_];     // input  [hi/lo]
__device__ __half g_iw16[2][2][(size_t)IN_ * H_];      // input W [gate][hi/lo]
__device__ unsigned g_arr[NGRP * 64];
__device__ unsigned g_gen[NGRP * 64];

__device__ __forceinline__ void cp16(uint32_t dst, const void* src) {
    asm volatile("cp.async.cg.shared.global [%0], [%1], 16;" :: "r"(dst), "l"(src) : "memory");
}
#define CP_COMMIT() asm volatile("cp.async.commit_group;" ::: "memory")
#define CP_WAIT0()  asm volatile("cp.async.wait_group 0;" ::: "memory")
template<int N> __device__ __forceinline__ void cp_wait() {
    asm volatile("cp.async.wait_group %0;" :: "n"(N) : "memory");
}

// ---- setup ----------------------------------------------------------------
__global__ void reset_barrier_kernel() {
    int i = threadIdx.x;
    if (i < NGRP * 64) { g_arr[i] = 0u; g_gen[i] = 0u; }
}
__global__ void wconvert_kernel(const float* __restrict__ rh_w,
                                const float* __restrict__ rt_w) {
    const size_t n = (size_t)L_ * H_ * H_;
    for (size_t i = (size_t)blockIdx.x * blockDim.x + threadIdx.x; i < n;
         i += (size_t)gridDim.x * blockDim.x) {
        float a = rh_w[i]; __half h = __float2half_rn(a);
        g_w16[0][0][i] = h; g_w16[0][1][i] = __float2half_rn(a - __half2float(h));
        float b = rt_w[i]; __half h2 = __float2half_rn(b);
        g_w16[1][0][i] = h2; g_w16[1][1][i] = __float2half_rn(b - __half2float(h2));
    }
}
__global__ void iwconvert_kernel(const float* __restrict__ w_h,
                                 const float* __restrict__ w_t) {
    const size_t n = (size_t)IN_ * H_;
    for (size_t i = (size_t)blockIdx.x * blockDim.x + threadIdx.x; i < n;
         i += (size_t)gridDim.x * blockDim.x) {
        float a = w_h[i]; __half h = __float2half_rn(a);
        g_iw16[0][0][i] = h; g_iw16[0][1][i] = __float2half_rn(a - __half2float(h));
        float b = w_t[i]; __half h2 = __float2half_rn(b);
        g_iw16[1][0][i] = h2; g_iw16[1][1][i] = __float2half_rn(b - __half2float(h2));
    }
}
__global__ void xconvert_kernel(const float* __restrict__ x) {
    const size_t n = (size_t)B_ * T_ * IN_;
    for (size_t i = (size_t)blockIdx.x * blockDim.x + threadIdx.x; i < n;
         i += (size_t)gridDim.x * blockDim.x) {
        float v = x[i]; __half h = __float2half_rn(v);
        g_x16[0][i] = h; g_x16[1][i] = __float2half_rn(v - __half2float(h));
    }
}
__global__ void sinit_kernel(const float* __restrict__ s0) {
    int i = blockIdx.x * blockDim.x + threadIdx.x;
    if (i < B_ * H_) {
        float v = s0[i]; __half h = __float2half_rn(v);
        g_s16[0][0][i] = h; g_s16[0][1][i] = __float2half_rn(v - __half2float(h));
    }
}

// ---- input GEMM via wmma fp16-split (proven R12) ---------------------------
#define XA_P 40
#define XB_P 136
__global__ __launch_bounds__(256) void xw_wmma_kernel()
{
    __shared__ __half As[2][128][XA_P];
    __shared__ __half Bs[2][32][XB_P];
    const uint32_t sbA = (uint32_t)__cvta_generic_to_shared(&As[0][0][0]);
    const uint32_t sbB = (uint32_t)__cvta_generic_to_shared(&Bs[0][0][0]);

    const int tid = threadIdx.x;
    const int warp = tid >> 5;
    const int wr = warp >> 1;
    const int wc = warp & 1;
    const int rb = blockIdx.y;
    const int jbase = blockIdx.x * 128;
    const int gate = jbase >> 10;
    const int joff = jbase & 1023;

    wmma::fragment<wmma::accumulator, 16, 16, 16, float> C[2][4];
    #pragma unroll
    for (int mi = 0; mi < 2; mi++)
        #pragma unroll
        for (int ni = 0; ni < 4; ni++) wmma::fill_fragment(C[mi][ni], 0.0f);

    for (int kt = 0; kt < 32; kt++) {
        __syncthreads();
        #pragma unroll
        for (int i = 0; i < 2; i++) {
            const int idx = i * 256 + tid;
            const int plane = idx >> 8;
            const int r = (idx & 255) >> 1;
            const int seg = idx & 1;
            const int rr = rb * 128 + r;
            const int xrow = (rr % B_) * T_ + (rr / B_);
            const __half* src = g_x16[plane] + (size_t)xrow * IN_ + kt * 32 + seg * 16;
            uint32_t dst = sbA + (uint32_t)((plane * 128 + r) * XA_P + seg * 16) * 2;
            cp16(dst, src); cp16(dst + 16, src + 8);
        }
        #pragma unroll
        for (int i = 0; i < 2; i++) {
            const int idx = i * 256 + tid;
            const int plane = idx >> 8;
            const int kr = (idx & 255) >> 3;
            const int seg = idx & 7;
            const __half* src = g_iw16[gate][plane] + (size_t)(kt * 32 + kr) * H_ + joff + seg * 16;
            uint32_t dst = sbB + (uint32_t)((plane * 32 + kr) * XB_P + seg * 16) * 2;
            cp16(dst, src); cp16(dst + 16, src + 8);
        }
        CP_COMMIT(); CP_WAIT0();
        __syncthreads();

        #pragma unroll
        for (int ks = 0; ks < 2; ks++) {
            const int ko = ks * 16;
            wmma::fragment<wmma::matrix_a, 16, 16, 16, __half, wmma::row_major> ah[2], al[2];
            wmma::fragment<wmma::matrix_b, 16, 16, 16, __half, wmma::row_major> bh[4], bl[4];
            #pragma unroll
            for (int mi = 0; mi < 2; mi++) {
                wmma::load_matrix_sync(ah[mi], &As[0][wr * 32 + mi * 16][ko], XA_P);
                wmma::load_matrix_sync(al[mi], &As[1][wr * 32 + mi * 16][ko], XA_P);
            }
            #pragma unroll
            for (int ni = 0; ni < 4; ni++) {
                wmma::load_matrix_sync(bh[ni], &Bs[0][ko][wc * 64 + ni * 16], XB_P);
                wmma::load_matrix_sync(bl[ni], &Bs[1][ko][wc * 64 + ni * 16], XB_P);
            }
            #pragma unroll
            for (int mi = 0; mi < 2; mi++)
                #pragma unroll
                for (int ni = 0; ni < 4; ni++) {
                    wmma::mma_sync(C[mi][ni], ah[mi], bh[ni], C[mi][ni]);
                    wmma::mma_sync(C[mi][ni], ah[mi], bl[ni], C[mi][ni]);
                    wmma::mma_sync(C[mi][ni], al[mi], bh[ni], C[mi][ni]);
                }
        }
    }

    #pragma unroll
    for (int mi = 0; mi < 2; mi++)
        #pragma unroll
        for (int ni = 0; ni < 4; ni++) {
            float* dst = g_xw + (size_t)(rb * 128 + wr * 32 + mi * 16) * (2 * H_)
                         + jbase + wc * 64 + ni * 16;
            wmma::store_matrix_sync(dst, C[mi][ni], 2 * H_, wmma::mem_row_major);
        }
}

// ---- fence-free scoped barrier ----------------------------------------------
__device__ __forceinline__ void group_sync(int gr, int step)
{
    __syncthreads();
    if (threadIdx.x == 0) {
        unsigned* arr = &g_arr[gr * 64];
        unsigned* gen = &g_gen[gr * 64];
        unsigned old;
        asm volatile("atom.acq_rel.gpu.global.add.u32 %0, [%1], 1;"
                     : "=r"(old) : "l"(arr) : "memory");
        if (old == (unsigned)(step * CPG + CPG - 1)) {
            asm volatile("st.release.gpu.global.u32 [%0], %1;"
                         :: "l"(gen), "r"((unsigned)(step + 1)) : "memory");
        } else {
            unsigned cur;
            do { asm volatile("ld.acquire.gpu.global.u32 %0, [%1];"
                              : "=r"(cur) : "l"(gen) : "memory");
            } while (cur <= (unsigned)step);
        }
    }
    __syncthreads();
}

// ---- persistent wmma recurrent kernel ----------------------------------------
// 128 CTAs = 2 groups x 64. CTA: 16 g-cols x 2 gates x 32 b.
// Weights: wmma A-frags loaded DIRECTLY from global (L2-resident), no smem.
// State: warp-private k-slices via per-warp cp.async groups -> no in-loop syncs.
__global__ __launch_bounds__(TPB, 1) void rhn_wmma_kernel(
    const float* __restrict__ rh_b, const float* __restrict__ rt_b,
    float* __restrict__ out)
{
    extern __shared__ __half smh[];
    float* pr = (float*)(smh + ST_H);
    const uint32_t sb = (uint32_t)__cvta_generic_to_shared(smh);

    const int tid  = threadIdx.x;
    const int wk   = tid >> 5;                 // warp = k-split 0..7
    const int lane = tid & 31;
    const int gb   = blockIdx.x;
    const int gr   = gb >> 6;
    const int c64  = gb & 63;
    const int bbase = gr * BPG;
    const int gbase = c64 * 16;

    // per-warp state chunk: chunk c covers k cols [c*128 + wk*16, +16), all 64 rows
    auto issue_chunk = [&](int pin, int c) {
        #pragma unroll
        for (int i = 0; i < 4; i++) {
            const int idx = i * 32 + lane;     // 0..127
            const int row = idx >> 1;          // 0..63
            const int halfseg = idx & 1;
            const int plane = row >> 5;
            const int b = bbase + (row & 31);
            const __half* src = g_s16[pin][plane] + (size_t)b * H_
                                + c * 128 + wk * 16 + halfseg * 8;
            cp16(sb + (uint32_t)(wk * WREG + row * WP + c * 16 + halfseg * 8) * 2, src);
        }
        CP_COMMIT();
    };

    // prologue: step-0 state
    #pragma unroll
    for (int c = 0; c < 8; c++) issue_chunk(0, c);

    int t = 0, l = 0;
    for (int step = 0; step < T_ * L_; step++) {
        const int pin = step & 1;

        // hoisted epilogue operands
        const int i0 = tid * 2, i1 = tid * 2 + 1;
        const int gl0 = i0 & 15, bq0 = i0 >> 4;
        const int gl1 = i1 & 15, bq1 = i1 >> 4;
        const int g0 = gbase + gl0, g1 = gbase + gl1;
        const int b0g = bbase + bq0, b1g = bbase + bq1;
        const float bh0 = rh_b[l * H_ + g0], bt0 = rt_b[l * H_ + g0];
        const float bh1 = rh_b[l * H_ + g1], bt1 = rt_b[l * H_ + g1];
        float xh0 = 0.f, xt0 = 0.f, xh1 = 0.f, xt1 = 0.f;
        if (l == 0) {
            const float* xw0 = g_xw + (size_t)(t * B_ + b0g) * (2 * H_);
            const float* xw1 = g_xw + (size_t)(t * B_ + b1g) * (2 * H_);
            xh0 = xw0[g0]; xt0 = xw0[H_ + g0];
            xh1 = xw1[g1]; xt1 = xw1[H_ + g1];
        }

        wmma::fragment<wmma::accumulator, 16, 16, 16, float> C[2][2];
        #pragma unroll
        for (int mi = 0; mi < 2; mi++) {
            wmma::fill_fragment(C[mi][0], 0.0f);
            wmma::fill_fragment(C[mi][1], 0.0f);
        }

        // A-frag double buffer (global loads, L2-resident weights)
        wmma::fragment<wmma::matrix_a, 16, 16, 16, __half, wmma::row_major> Ah[2][2], Al[2][2];
        const size_t loff = (size_t)l * H_ * H_ + (size_t)gbase * H_;
        {
            const int kg = wk * 16;
            #pragma unroll
            for (int mi = 0; mi < 2; mi++) {
                wmma::load_matrix_sync(Ah[0][mi], g_w16[mi][0] + loff + kg, H_);
                wmma::load_matrix_sync(Al[0][mi], g_w16[mi][1] + loff + kg, H_);
            }
        }

        const __half* wreg = smh + wk * WREG;
        #pragma unroll
        for (int kt = 0; kt < 8; kt++) {
            // own state chunk kt resident (per-warp wait, no block sync)
            switch (kt) {
                case 0: cp_wait<7>(); break;  case 1: cp_wait<6>(); break;
                case 2: cp_wait<5>(); break;  case 3: cp_wait<4>(); break;
                case 4: cp_wait<3>(); break;  case 5: cp_wait<2>(); break;
                case 6: cp_wait<1>(); break;  default: cp_wait<0>(); break;
            }
            const int cur = kt & 1, nxt = cur ^ 1;
            if (kt < 7) {
                const int kg = (kt + 1) * 128 + wk * 16;
                #pragma unroll
                for (int mi = 0; mi < 2; mi++) {
                    wmma::load_matrix_sync(Ah[nxt][mi], g_w16[mi][0] + loff + kg, H_);
                    wmma::load_matrix_sync(Al[nxt][mi], g_w16[mi][1] + loff + kg, H_);
                }
            }
            wmma::fragment<wmma::matrix_b, 16, 16, 16, __half, wmma::col_major> Bh[2], Bl[2];
            #pragma unroll
            for (int ni = 0; ni < 2; ni++) {
                wmma::load_matrix_sync(Bh[ni], wreg + (ni * 16) * WP + kt * 16, WP);
                wmma::load_matrix_sync(Bl[ni], wreg + ((32 + ni * 16)) * WP + kt * 16, WP);
            }
            #pragma unroll
            for (int mi = 0; mi < 2; mi++)
                #pragma unroll
                for (int ni = 0; ni < 2; ni++) {
                    wmma::mma_sync(C[mi][ni], Ah[cur][mi], Bh[ni], C[mi][ni]);
                    wmma::mma_sync(C[mi][ni], Ah[cur][mi], Bl[ni], C[mi][ni]);
                    wmma::mma_sync(C[mi][ni], Al[cur][mi], Bh[ni], C[mi][ni]);
                }
        }

        // partials
        {
            float* base = pr + (size_t)wk * 32 * PRP;
            #pragma unroll
            for (int mi = 0; mi < 2; mi++)
                #pragma unroll
                for (int ni = 0; ni < 2; ni++)
                    wmma::store_matrix_sync(base + mi * 16 * PRP + ni * 16,
                                            C[mi][ni], PRP, wmma::mem_row_major);
        }
        __syncthreads();

        // reduce + fused epilogue (2 outputs/thread); so = hi+lo from smem
        {
            float ph0 = bh0 + xh0, pt0 = bt0 + xt0;
            float ph1 = bh1 + xh1, pt1 = bt1 + xt1;
            #pragma unroll
            for (int w = 0; w < 8; w++) {
                const float* bk_ = pr + (size_t)w * 32 * PRP;
                ph0 += bk_[gl0 * PRP + bq0];
                pt0 += bk_[(16 + gl0) * PRP + bq0];
                ph1 += bk_[gl1 * PRP + bq1];
                pt1 += bk_[(16 + gl1) * PRP + bq1];
            }
            // so from warp-private regions: k index g -> region ((g>>4)&7), col (g>>7)*16+(g&15)
            const int w0 = (g0 >> 4) & 7, col0 = (g0 >> 7) * 16 + (g0 & 15);
            const int w1 = (g1 >> 4) & 7, col1 = (g1 >> 7) * 16 + (g1 & 15);
            const float so0 = __half2float(smh[w0 * WREG + bq0 * WP + col0])
                            + __half2float(smh[w0 * WREG + (32 + bq0) * WP + col0]);
            const float so1 = __half2float(smh[w1 * WREG + bq1 * WP + col1])
                            + __half2float(smh[w1 * WREG + (32 + bq1) * WP + col1]);
            const float hh0 = tanhf(ph0), hh1 = tanhf(ph1);
            const float tg0 = 1.0f / (1.0f + expf(-pt0));
            const float tg1 = 1.0f / (1.0f + expf(-pt1));
            const float sn0 = fmaf(hh0 - so0, tg0, so0);
            const float sn1 = fmaf(hh1 - so1, tg1, so1);
            const __half a0 = __float2half_rn(sn0);
            const __half a1 = __float2half_rn(sn1);
            const __half c0 = __float2half_rn(sn0 - __half2float(a0));
            const __half c1 = __float2half_rn(sn1 - __half2float(a1));
            const size_t si0 = (size_t)b0g * H_ + g0;
            const size_t si1 = (size_t)b1g * H_ + g1;
            unsigned short u;
            u = __half_as_ushort(a0);
            asm volatile("st.global.cg.u16 [%0], %1;" :: "l"(&g_s16[pin ^ 1][0][si0]), "h"(u));
            u = __half_as_ushort(c0);
            asm volatile("st.global.cg.u16 [%0], %1;" :: "l"(&g_s16[pin ^ 1][1][si0]), "h"(u));
            u = __half_as_ushort(a1);
            asm volatile("st.global.cg.u16 [%0], %1;" :: "l"(&g_s16[pin ^ 1][0][si1]), "h"(u));
            u = __half_as_ushort(c1);
            asm volatile("st.global.cg.u16 [%0], %1;" :: "l"(&g_s16[pin ^ 1][1][si1]), "h"(u));
            if (l == L_ - 1) {
                out[((size_t)b0g * T_ + t) * H_ + g0] = sn0;
                out[((size_t)b1g * T_ + t) * H_ + g1] = sn1;
                if (t == T_ - 1) {
                    out[(size_t)B_ * T_ * H_ + (size_t)b0g * H_ + g0] = sn0;
                    out[(size_t)B_ * T_ * H_ + (size_t)b1g * H_ + g1] = sn1;
                }
            }
        }

        int tn = t, ln = l + 1;
        if (ln == L_) { ln = 0; tn = t + 1; }
        if (step != T_ * L_ - 1) {
            group_sync(gr, step);
            #pragma unroll
            for (int c = 0; c < 8; c++) issue_chunk(pin ^ 1, c);
        }
        t = tn; l = ln;
    }
}

// ---------------------------------------------------------------------------
extern "C" void kernel_launch(void* const* d_in, const int* in_sizes, int n_in,
                              void* d_out, int out_size)
{
    const float* input = (const float*)d_in[0];
    const float* s0    = (const float*)d_in[1];
    const float* w_h   = (const float*)d_in[2];
    const float* w_t   = (const float*)d_in[3];
    const float* rh_w  = (const float*)d_in[4];
    const float* rh_b  = (const float*)d_in[5];
    const float* rt_w  = (const float*)d_in[6];
    const float* rt_b  = (const float*)d_in[7];
    float* out = (float*)d_out;

    static bool attr_set = false;
    if (!attr_set) {
        cudaFuncSetAttribute(rhn_wmma_kernel,
                             cudaFuncAttributeMaxDynamicSharedMemorySize, SMEM_BYTES);
        attr_set = true;
    }

    reset_barrier_kernel<<<1, 256>>>();
    sinit_kernel<<<(B_ * H_ + 255) / 256, 256>>>(s0);
    wconvert_kernel<<<2048, 256>>>(rh_w, rt_w);
    iwconvert_kernel<<<1024, 256>>>(w_h, w_t);
    xconvert_kernel<<<4096, 256>>>(input);
    {
        dim3 grid(16, 256);
        xw_wmma_kernel<<<grid, 256>>>();
    }
    rhn_wmma_kernel<<<NC, TPB, SMEM_BYTES>>>(rh_b, rt_b, out);
}

// round 15
// speedup vs baseline: 1.3697x; 1.3697x over previous
#include <cuda_runtime.h>
#include <cuda_fp16.h>
#include <mma.h>
#include <math.h>
#include <stdint.h>

#define B_  64
#define T_  512
#define IN_ 1024
#define H_  1024
#define L_  5
#define NC   128
#define TPB  256
#define NGRP 2
#define CPG  64
#define BPG  32
typedef unsigned long long ull;
using namespace nvcuda;

// recurrent smem (halves): 3 slots x 128 rows x 136
//  rows 0-31 Whi, 32-63 Wlo, 64-95 Shi, 96-127 Slo
#define WPITCH 136
#define SLOT_H (128 * WPITCH)                 // 17408 halves = 34816 B
#define PART_F (3 * SLOT_H / 2)               // float offset of partials
#define PRP 36
#define SMEM_BYTES (3 * SLOT_H * 2 + 4 * 32 * PRP * 4)  // 104448+18432 = 122880

__device__ float  g_xw[(size_t)B_ * T_ * 2 * H_];
__device__ __half g_w16[2][2][(size_t)L_ * H_ * H_];   // recurrent W [gate][hi/lo]
__device__ __half g_s16[2][2][B_ * H_];                // state [buf][hi/lo]
__device__ __half g_x16[2][(size_t)B_ * T_ * IN_];     // input  [hi/lo]
__device__ __half g_iw16[2][2][(size_t)IN_ * H_];      // input W [gate][hi/lo]
__device__ unsigned g_arr[NGRP * 64];
__device__ unsigned g_gen[NGRP * 64];

__device__ __forceinline__ void cp16(uint32_t dst, const void* src) {
    asm volatile("cp.async.cg.shared.global [%0], [%1], 16;" :: "r"(dst), "l"(src) : "memory");
}
#define CP_COMMIT() asm volatile("cp.async.commit_group;" ::: "memory")
#define CP_WAIT0()  asm volatile("cp.async.wait_group 0;" ::: "memory")
#define CP_WAIT1()  asm volatile("cp.async.wait_group 1;" ::: "memory")

// ---- setup ----------------------------------------------------------------
__global__ void reset_barrier_kernel() {
    int i = threadIdx.x;
    if (i < NGRP * 64) { g_arr[i] = 0u; g_gen[i] = 0u; }
}
__global__ void wconvert_kernel(const float* __restrict__ rh_w,
                                const float* __restrict__ rt_w) {
    const size_t n = (size_t)L_ * H_ * H_;
    for (size_t i = (size_t)blockIdx.x * blockDim.x + threadIdx.x; i < n;
         i += (size_t)gridDim.x * blockDim.x) {
        float a = rh_w[i]; __half h = __float2half_rn(a);
        g_w16[0][0][i] = h; g_w16[0][1][i] = __float2half_rn(a - __half2float(h));
        float b = rt_w[i]; __half h2 = __float2half_rn(b);
        g_w16[1][0][i] = h2; g_w16[1][1][i] = __float2half_rn(b - __half2float(h2));
    }
}
__global__ void iwconvert_kernel(const float* __restrict__ w_h,
                                 const float* __restrict__ w_t) {
    const size_t n = (size_t)IN_ * H_;
    for (size_t i = (size_t)blockIdx.x * blockDim.x + threadIdx.x; i < n;
         i += (size_t)gridDim.x * blockDim.x) {
        float a = w_h[i]; __half h = __float2half_rn(a);
        g_iw16[0][0][i] = h; g_iw16[0][1][i] = __float2half_rn(a - __half2float(h));
        float b = w_t[i]; __half h2 = __float2half_rn(b);
        g_iw16[1][0][i] = h2; g_iw16[1][1][i] = __float2half_rn(b - __half2float(h2));
    }
}
__global__ void xconvert_kernel(const float* __restrict__ x) {
    const size_t n = (size_t)B_ * T_ * IN_;
    for (size_t i = (size_t)blockIdx.x * blockDim.x + threadIdx.x; i < n;
         i += (size_t)gridDim.x * blockDim.x) {
        float v = x[i]; __half h = __float2half_rn(v);
        g_x16[0][i] = h; g_x16[1][i] = __float2half_rn(v - __half2float(h));
    }
}
__global__ void sinit_kernel(const float* __restrict__ s0) {
    int i = blockIdx.x * blockDim.x + threadIdx.x;
    if (i < B_ * H_) {
        float v = s0[i]; __half h = __float2half_rn(v);
        g_s16[0][0][i] = h; g_s16[0][1][i] = __float2half_rn(v - __half2float(h));
    }
}

// ---- input GEMM via wmma fp16-split (proven R12) ---------------------------
#define XA_P 40
#define XB_P 136
__global__ __launch_bounds__(256) void xw_wmma_kernel()
{
    __shared__ __half As[2][128][XA_P];
    __shared__ __half Bs[2][32][XB_P];
    const uint32_t sbA = (uint32_t)__cvta_generic_to_shared(&As[0][0][0]);
    const uint32_t sbB = (uint32_t)__cvta_generic_to_shared(&Bs[0][0][0]);

    const int tid = threadIdx.x;
    const int warp = tid >> 5;
    const int wr = warp >> 1;
    const int wc = warp & 1;
    const int rb = blockIdx.y;
    const int jbase = blockIdx.x * 128;
    const int gate = jbase >> 10;
    const int joff = jbase & 1023;

    wmma::fragment<wmma::accumulator, 16, 16, 16, float> C[2][4];
    #pragma unroll
    for (int mi = 0; mi < 2; mi++)
        #pragma unroll
        for (int ni = 0; ni < 4; ni++) wmma::fill_fragment(C[mi][ni], 0.0f);

    for (int kt = 0; kt < 32; kt++) {
        __syncthreads();
        #pragma unroll
        for (int i = 0; i < 2; i++) {
            const int idx = i * 256 + tid;
            const int plane = idx >> 8;
            const int r = (idx & 255) >> 1;
            const int seg = idx & 1;
            const int rr = rb * 128 + r;
            const int xrow = (rr % B_) * T_ + (rr / B_);
            const __half* src = g_x16[plane] + (size_t)xrow * IN_ + kt * 32 + seg * 16;
            uint32_t dst = sbA + (uint32_t)((plane * 128 + r) * XA_P + seg * 16) * 2;
            cp16(dst, src); cp16(dst + 16, src + 8);
        }
        #pragma unroll
        for (int i = 0; i < 2; i++) {
            const int idx = i * 256 + tid;
            const int plane = idx >> 8;
            const int kr = (idx & 255) >> 3;
            const int seg = idx & 7;
            const __half* src = g_iw16[gate][plane] + (size_t)(kt * 32 + kr) * H_ + joff + seg * 16;
            uint32_t dst = sbB + (uint32_t)((plane * 32 + kr) * XB_P + seg * 16) * 2;
            cp16(dst, src); cp16(dst + 16, src + 8);
        }
        CP_COMMIT(); CP_WAIT0();
        __syncthreads();

        #pragma unroll
        for (int ks = 0; ks < 2; ks++) {
            const int ko = ks * 16;
            wmma::fragment<wmma::matrix_a, 16, 16, 16, __half, wmma::row_major> ah[2], al[2];
            wmma::fragment<wmma::matrix_b, 16, 16, 16, __half, wmma::row_major> bh[4], bl[4];
            #pragma unroll
            for (int mi = 0; mi < 2; mi++) {
                wmma::load_matrix_sync(ah[mi], &As[0][wr * 32 + mi * 16][ko], XA_P);
                wmma::load_matrix_sync(al[mi], &As[1][wr * 32 + mi * 16][ko], XA_P);
            }
            #pragma unroll
            for (int ni = 0; ni < 4; ni++) {
                wmma::load_matrix_sync(bh[ni], &Bs[0][ko][wc * 64 + ni * 16], XB_P);
                wmma::load_matrix_sync(bl[ni], &Bs[1][ko][wc * 64 + ni * 16], XB_P);
            }
            #pragma unroll
            for (int mi = 0; mi < 2; mi++)
                #pragma unroll
                for (int ni = 0; ni < 4; ni++) {
                    wmma::mma_sync(C[mi][ni], ah[mi], bh[ni], C[mi][ni]);
                    wmma::mma_sync(C[mi][ni], ah[mi], bl[ni], C[mi][ni]);
                    wmma::mma_sync(C[mi][ni], al[mi], bh[ni], C[mi][ni]);
                }
        }
    }

    #pragma unroll
    for (int mi = 0; mi < 2; mi++)
        #pragma unroll
        for (int ni = 0; ni < 4; ni++) {
            float* dst = g_xw + (size_t)(rb * 128 + wr * 32 + mi * 16) * (2 * H_)
                         + jbase + wc * 64 + ni * 16;
            wmma::store_matrix_sync(dst, C[mi][ni], 2 * H_, wmma::mem_row_major);
        }
}

// ---- fence-free scoped barrier ----------------------------------------------
__device__ __forceinline__ void group_sync(int gr, int step)
{
    __syncthreads();
    if (threadIdx.x == 0) {
        unsigned* arr = &g_arr[gr * 64];
        unsigned* gen = &g_gen[gr * 64];
        unsigned old;
        asm volatile("atom.acq_rel.gpu.global.add.u32 %0, [%1], 1;"
                     : "=r"(old) : "l"(arr) : "memory");
        if (old == (unsigned)(step * CPG + CPG - 1)) {
            asm volatile("st.release.gpu.global.u32 [%0], %1;"
                         :: "l"(gen), "r"((unsigned)(step + 1)) : "memory");
        } else {
            unsigned cur;
            do { asm volatile("ld.acquire.gpu.global.u32 %0, [%1];"
                              : "=r"(cur) : "l"(gen) : "memory");
            } while (cur <= (unsigned)step);
        }
    }
    __syncthreads();
}

// ---- persistent wmma recurrent kernel ----------------------------------------
// 128 CTAs = 2 groups x 64. CTA: 16 g-cols x 2 gates x 32 b.
// 8 warps = 4 k-split x 2 n-split; warp tile m32 x n16; 3 mma terms; ring-3.
__global__ __launch_bounds__(TPB, 1) void rhn_wmma_kernel(
    const float* __restrict__ rh_b, const float* __restrict__ rt_b,
    float* __restrict__ out)
{
    extern __shared__ __half smh[];
    float* pr = (float*)smh + PART_F;
    const uint32_t sb = (uint32_t)__cvta_generic_to_shared(smh);

    const int tid  = threadIdx.x;
    const int warp = tid >> 5;
    const int wk   = warp >> 1;                // k-split 0..3
    const int wn   = warp & 1;                 // n-half 0..1
    const int gb   = blockIdx.x;
    const int gr   = gb >> 6;
    const int c64  = gb & 63;
    const int bbase = gr * BPG;
    const int gbase = c64 * 16;

    auto issue_w = [&](int l, int kt, int slot) {   // rows 0-63: 4 cp16/thread
        #pragma unroll
        for (int i = 0; i < 4; i++) {
            const int idx = i * 256 + tid;
            const int row = idx >> 4;
            const int seg = idx & 15;
            const int plane = row >> 5;
            const int rr = row & 31;
            const int gate = rr >> 4;
            const int g = gbase + (rr & 15);
            const __half* src = g_w16[gate][plane] + (size_t)l * H_ * H_
                                + (size_t)g * H_ + kt * 128 + seg * 8;
            cp16(sb + (uint32_t)(slot * SLOT_H + row * WPITCH + seg * 8) * 2, src);
        }
    };
    auto issue_s = [&](int pin, int kt, int slot) { // rows 64-127: 4 cp16/thread
        #pragma unroll
        for (int i = 0; i < 4; i++) {
            const int idx = i * 256 + tid;
            const int row = idx >> 4;
            const int seg = idx & 15;
            const int plane = row >> 5;
            const int b = bbase + (row & 31);
            const __half* src = g_s16[pin][plane] + (size_t)b * H_ + kt * 128 + seg * 8;
            cp16(sb + (uint32_t)(slot * SLOT_H + (64 + row) * WPITCH + seg * 8) * 2, src);
        }
    };

    // prologue
    issue_w(0, 0, 0); CP_COMMIT();
    issue_s(0, 0, 0); CP_COMMIT();
    issue_w(0, 1, 1); issue_s(0, 1, 1); CP_COMMIT();

    int t = 0, l = 0;
    for (int step = 0; step < T_ * L_; step++) {
        const int pin = step & 1;

        // hoisted epilogue operands: thread -> 2 (g,b) pairs
        const int i0 = tid * 2, i1 = tid * 2 + 1;
        const int gl0 = i0 & 15, bq0 = i0 >> 4;
        const int gl1 = i1 & 15, bq1 = i1 >> 4;
        const int g0 = gbase + gl0, g1 = gbase + gl1;
        const int b0g = bbase + bq0, b1g = bbase + bq1;
        const size_t si0 = (size_t)b0g * H_ + g0;
        const size_t si1 = (size_t)b1g * H_ + g1;
        const float bh0 = rh_b[l * H_ + g0], bt0 = rt_b[l * H_ + g0];
        const float bh1 = rh_b[l * H_ + g1], bt1 = rt_b[l * H_ + g1];
        const float so0 = __half2float(__ldcg(&g_s16[pin][0][si0]))
                        + __half2float(__ldcg(&g_s16[pin][1][si0]));
        const float so1 = __half2float(__ldcg(&g_s16[pin][0][si1]))
                        + __half2float(__ldcg(&g_s16[pin][1][si1]));
        float xh0 = 0.f, xt0 = 0.f, xh1 = 0.f, xt1 = 0.f;
        if (l == 0) {
            const float* xw0 = g_xw + (size_t)(t * B_ + b0g) * (2 * H_);
            const float* xw1 = g_xw + (size_t)(t * B_ + b1g) * (2 * H_);
            xh0 = xw0[g0]; xt0 = xw0[H_ + g0];
            xh1 = xw1[g1]; xt1 = xw1[H_ + g1];
        }

        wmma::fragment<wmma::accumulator, 16, 16, 16, float> C[2];
        wmma::fill_fragment(C[0], 0.0f);
        wmma::fill_fragment(C[1], 0.0f);

        for (int kt = 0; kt < 8; kt++) {
            if (kt < 7) { CP_WAIT1(); } else { CP_WAIT0(); }
            __syncthreads();
            if (kt < 6) { issue_w(l, kt + 2, (kt + 2) % 3); issue_s(pin, kt + 2, (kt + 2) % 3); CP_COMMIT(); }

            const __half* slot = smh + (kt % 3) * SLOT_H;
            #pragma unroll
            for (int ks = 0; ks < 2; ks++) {
                const int koff = wk * 32 + ks * 16;
                wmma::fragment<wmma::matrix_b, 16, 16, 16, __half, wmma::col_major> bh, bl;
                wmma::load_matrix_sync(bh, slot + (64 + wn * 16) * WPITCH + koff, WPITCH);
                wmma::load_matrix_sync(bl, slot + (96 + wn * 16) * WPITCH + koff, WPITCH);
                #pragma unroll
                for (int mi = 0; mi < 2; mi++) {
                    wmma::fragment<wmma::matrix_a, 16, 16, 16, __half, wmma::row_major> ah, al;
                    wmma::load_matrix_sync(ah, slot + (mi * 16) * WPITCH + koff, WPITCH);
                    wmma::load_matrix_sync(al, slot + (32 + mi * 16) * WPITCH + koff, WPITCH);
                    wmma::mma_sync(C[mi], ah, bh, C[mi]);
                    wmma::mma_sync(C[mi], ah, bl, C[mi]);
                    wmma::mma_sync(C[mi], al, bh, C[mi]);
                }
            }
        }

        // partials: pr[wk][m 0..31][n 0..31], wn warps write disjoint n-halves
        {
            float* base = pr + (size_t)wk * 32 * PRP + wn * 16;
            #pragma unroll
            for (int mi = 0; mi < 2; mi++)
                wmma::store_matrix_sync(base + mi * 16 * PRP, C[mi], PRP,
                                        wmma::mem_row_major);
        }
        __syncthreads();

        // reduce (4 levels) + fused epilogue (2 outputs/thread)
        {
            float ph0 = bh0 + xh0, pt0 = bt0 + xt0;
            float ph1 = bh1 + xh1, pt1 = bt1 + xt1;
            #pragma unroll
            for (int w = 0; w < 4; w++) {
                const float* bk_ = pr + (size_t)w * 32 * PRP;
                ph0 += bk_[gl0 * PRP + bq0];
                pt0 += bk_[(16 + gl0) * PRP + bq0];
                ph1 += bk_[gl1 * PRP + bq1];
                pt1 += bk_[(16 + gl1) * PRP + bq1];
            }
            const float hh0 = tanhf(ph0), hh1 = tanhf(ph1);
            const float tg0 = 1.0f / (1.0f + expf(-pt0));
            const float tg1 = 1.0f / (1.0f + expf(-pt1));
            const float sn0 = fmaf(hh0 - so0, tg0, so0);
            const float sn1 = fmaf(hh1 - so1, tg1, so1);
            const __half a0 = __float2half_rn(sn0);
            const __half a1 = __float2half_rn(sn1);
            const __half c0 = __float2half_rn(sn0 - __half2float(a0));
            const __half c1 = __float2half_rn(sn1 - __half2float(a1));
            unsigned short u;
            u = __half_as_ushort(a0);
            asm volatile("st.global.cg.u16 [%0], %1;" :: "l"(&g_s16[pin ^ 1][0][si0]), "h"(u));
            u = __half_as_ushort(c0);
            asm volatile("st.global.cg.u16 [%0], %1;" :: "l"(&g_s16[pin ^ 1][1][si0]), "h"(u));
            u = __half_as_ushort(a1);
            asm volatile("st.global.cg.u16 [%0], %1;" :: "l"(&g_s16[pin ^ 1][0][si1]), "h"(u));
            u = __half_as_ushort(c1);
            asm volatile("st.global.cg.u16 [%0], %1;" :: "l"(&g_s16[pin ^ 1][1][si1]), "h"(u));
            if (l == L_ - 1) {
                out[((size_t)b0g * T_ + t) * H_ + g0] = sn0;
                out[((size_t)b1g * T_ + t) * H_ + g1] = sn1;
                if (t == T_ - 1) {
                    out[(size_t)B_ * T_ * H_ + (size_t)b0g * H_ + g0] = sn0;
                    out[(size_t)B_ * T_ * H_ + (size_t)b1g * H_ + g1] = sn1;
                }
            }
        }

        int tn = t, ln = l + 1;
        if (ln == L_) { ln = 0; tn = t + 1; }
        const bool last = (step == T_ * L_ - 1);
        if (!last) {
            issue_w(ln, 0, 0); CP_COMMIT();     // W0' (read-only, pre-barrier)
            group_sync(gr, step);
            issue_s(pin ^ 1, 0, 0); CP_COMMIT();
            issue_w(ln, 1, 1); issue_s(pin ^ 1, 1, 1); CP_COMMIT();
        }
        t = tn; l = ln;
    }
}

// ---------------------------------------------------------------------------
extern "C" void kernel_launch(void* const* d_in, const int* in_sizes, int n_in,
                              void* d_out, int out_size)
{
    const float* input = (const float*)d_in[0];
    const float* s0    = (const float*)d_in[1];
    const float* w_h   = (const float*)d_in[2];
    const float* w_t   = (const float*)d_in[3];
    const float* rh_w  = (const float*)d_in[4];
    const float* rh_b  = (const float*)d_in[5];
    const float* rt_w  = (const float*)d_in[6];
    const float* rt_b  = (const float*)d_in[7];
    float* out = (float*)d_out;

    static bool attr_set = false;
    if (!attr_set) {
        cudaFuncSetAttribute(rhn_wmma_kernel,
                             cudaFuncAttributeMaxDynamicSharedMemorySize, SMEM_BYTES);
        attr_set = true;
    }

    reset_barrier_kernel<<<1, 256>>>();
    sinit_kernel<<<(B_ * H_ + 255) / 256, 256>>>(s0);
    wconvert_kernel<<<2048, 256>>>(rh_w, rt_w);
    iwconvert_kernel<<<1024, 256>>>(w_h, w_t);
    xconvert_kernel<<<4096, 256>>>(input);
    {
        dim3 grid(16, 256);
        xw_wmma_kernel<<<grid, 256>>>();
    }
    rhn_wmma_kernel<<<NC, TPB, SMEM_BYTES>>>(rh_b, rt_b, out);
}

// round 16
// speedup vs baseline: 1.4287x; 1.0431x over previous
#include <cuda_runtime.h>
#include <cuda_fp16.h>
#include <mma.h>
#include <math.h>
#include <stdint.h>

#define B_  64
#define T_  512
#define IN_ 1024
#define H_  1024
#define L_  5
#define NC   128
#define TPB  256
#define NGRP 2
#define CPG  64
#define BPG  32
typedef unsigned long long ull;
using namespace nvcuda;

// recurrent smem (halves): 3 slots x 128 rows x 136
//  rows 0-31 Whi, 32-63 Wlo, 64-95 Shi, 96-127 Slo
#define WPITCH 136
#define SLOT_H (128 * WPITCH)                 // 17408 halves = 34816 B
#define PART_F (3 * SLOT_H / 2)               // float offset of partials
#define PRP 36
#define SMEM_BYTES (3 * SLOT_H * 2 + 8 * 32 * PRP * 4)  // 104448+36864 = 141312

__device__ float  g_xw[(size_t)B_ * T_ * 2 * H_];
__device__ float  g_state[2][B_ * H_];
__device__ __half g_w16[2][2][(size_t)L_ * H_ * H_];   // recurrent W [gate][hi/lo]
__device__ __half g_s16[2][2][B_ * H_];                // state [buf][hi/lo]
__device__ __half g_x16[2][(size_t)B_ * T_ * IN_];     // input  [hi/lo]
__device__ __half g_iw16[2][2][(size_t)IN_ * H_];      // input W [gate][hi/lo]
__device__ unsigned g_arr[NGRP * 64];
__device__ unsigned g_gen[NGRP * 64];

__device__ __forceinline__ void cp16(uint32_t dst, const void* src) {
    asm volatile("cp.async.cg.shared.global [%0], [%1], 16;" :: "r"(dst), "l"(src) : "memory");
}
#define CP_COMMIT() asm volatile("cp.async.commit_group;" ::: "memory")
#define CP_WAIT0()  asm volatile("cp.async.wait_group 0;" ::: "memory")
#define CP_WAIT1()  asm volatile("cp.async.wait_group 1;" ::: "memory")

// ---- setup ----------------------------------------------------------------
__global__ void reset_barrier_kernel() {
    int i = threadIdx.x;
    if (i < NGRP * 64) { g_arr[i] = 0u; g_gen[i] = 0u; }
}
__global__ void wconvert_kernel(const float* __restrict__ rh_w,
                                const float* __restrict__ rt_w) {
    const size_t n = (size_t)L_ * H_ * H_;
    for (size_t i = (size_t)blockIdx.x * blockDim.x + threadIdx.x; i < n;
         i += (size_t)gridDim.x * blockDim.x) {
        float a = rh_w[i]; __half h = __float2half_rn(a);
        g_w16[0][0][i] = h; g_w16[0][1][i] = __float2half_rn(a - __half2float(h));
        float b = rt_w[i]; __half h2 = __float2half_rn(b);
        g_w16[1][0][i] = h2; g_w16[1][1][i] = __float2half_rn(b - __half2float(h2));
    }
}
__global__ void iwconvert_kernel(const float* __restrict__ w_h,
                                 const float* __restrict__ w_t) {
    const size_t n = (size_t)IN_ * H_;
    for (size_t i = (size_t)blockIdx.x * blockDim.x + threadIdx.x; i < n;
         i += (size_t)gridDim.x * blockDim.x) {
        float a = w_h[i]; __half h = __float2half_rn(a);
        g_iw16[0][0][i] = h; g_iw16[0][1][i] = __float2half_rn(a - __half2float(h));
        float b = w_t[i]; __half h2 = __float2half_rn(b);
        g_iw16[1][0][i] = h2; g_iw16[1][1][i] = __float2half_rn(b - __half2float(h2));
    }
}
__global__ void xconvert_kernel(const float* __restrict__ x) {
    const size_t n = (size_t)B_ * T_ * IN_;
    for (size_t i = (size_t)blockIdx.x * blockDim.x + threadIdx.x; i < n;
         i += (size_t)gridDim.x * blockDim.x) {
        float v = x[i]; __half h = __float2half_rn(v);
        g_x16[0][i] = h; g_x16[1][i] = __float2half_rn(v - __half2float(h));
    }
}
__global__ void sinit_kernel(const float* __restrict__ s0) {
    int i = blockIdx.x * blockDim.x + threadIdx.x;
    if (i < B_ * H_) {
        float v = s0[i]; __half h = __float2half_rn(v);
        g_s16[0][0][i] = h; g_s16[0][1][i] = __float2half_rn(v - __half2float(h));
    }
}

// ---- input GEMM via wmma fp16-split (proven R12) ---------------------------
#define XA_P 40
#define XB_P 136
__global__ __launch_bounds__(256) void xw_wmma_kernel()
{
    __shared__ __half As[2][128][XA_P];
    __shared__ __half Bs[2][32][XB_P];
    const uint32_t sbA = (uint32_t)__cvta_generic_to_shared(&As[0][0][0]);
    const uint32_t sbB = (uint32_t)__cvta_generic_to_shared(&Bs[0][0][0]);

    const int tid = threadIdx.x;
    const int warp = tid >> 5;
    const int wr = warp >> 1;
    const int wc = warp & 1;
    const int rb = blockIdx.y;
    const int jbase = blockIdx.x * 128;
    const int gate = jbase >> 10;
    const int joff = jbase & 1023;

    wmma::fragment<wmma::accumulator, 16, 16, 16, float> C[2][4];
    #pragma unroll
    for (int mi = 0; mi < 2; mi++)
        #pragma unroll
        for (int ni = 0; ni < 4; ni++) wmma::fill_fragment(C[mi][ni], 0.0f);

    for (int kt = 0; kt < 32; kt++) {
        __syncthreads();
        #pragma unroll
        for (int i = 0; i < 2; i++) {
            const int idx = i * 256 + tid;
            const int plane = idx >> 8;
            const int r = (idx & 255) >> 1;
            const int seg = idx & 1;
            const int rr = rb * 128 + r;
            const int xrow = (rr % B_) * T_ + (rr / B_);
            const __half* src = g_x16[plane] + (size_t)xrow * IN_ + kt * 32 + seg * 16;
            uint32_t dst = sbA + (uint32_t)((plane * 128 + r) * XA_P + seg * 16) * 2;
            cp16(dst, src); cp16(dst + 16, src + 8);
        }
        #pragma unroll
        for (int i = 0; i < 2; i++) {
            const int idx = i * 256 + tid;
            const int plane = idx >> 8;
            const int kr = (idx & 255) >> 3;
            const int seg = idx & 7;
            const __half* src = g_iw16[gate][plane] + (size_t)(kt * 32 + kr) * H_ + joff + seg * 16;
            uint32_t dst = sbB + (uint32_t)((plane * 32 + kr) * XB_P + seg * 16) * 2;
            cp16(dst, src); cp16(dst + 16, src + 8);
        }
        CP_COMMIT(); CP_WAIT0();
        __syncthreads();

        #pragma unroll
        for (int ks = 0; ks < 2; ks++) {
            const int ko = ks * 16;
            wmma::fragment<wmma::matrix_a, 16, 16, 16, __half, wmma::row_major> ah[2], al[2];
            wmma::fragment<wmma::matrix_b, 16, 16, 16, __half, wmma::row_major> bh[4], bl[4];
            #pragma unroll
            for (int mi = 0; mi < 2; mi++) {
                wmma::load_matrix_sync(ah[mi], &As[0][wr * 32 + mi * 16][ko], XA_P);
                wmma::load_matrix_sync(al[mi], &As[1][wr * 32 + mi * 16][ko], XA_P);
            }
            #pragma unroll
            for (int ni = 0; ni < 4; ni++) {
                wmma::load_matrix_sync(bh[ni], &Bs[0][ko][wc * 64 + ni * 16], XB_P);
                wmma::load_matrix_sync(bl[ni], &Bs[1][ko][wc * 64 + ni * 16], XB_P);
            }
            #pragma unroll
            for (int mi = 0; mi < 2; mi++)
                #pragma unroll
                for (int ni = 0; ni < 4; ni++) {
                    wmma::mma_sync(C[mi][ni], ah[mi], bh[ni], C[mi][ni]);
                    wmma::mma_sync(C[mi][ni], ah[mi], bl[ni], C[mi][ni]);
                    wmma::mma_sync(C[mi][ni], al[mi], bh[ni], C[mi][ni]);
                }
        }
    }

    #pragma unroll
    for (int mi = 0; mi < 2; mi++)
        #pragma unroll
        for (int ni = 0; ni < 4; ni++) {
            float* dst = g_xw + (size_t)(rb * 128 + wr * 32 + mi * 16) * (2 * H_)
                         + jbase + wc * 64 + ni * 16;
            wmma::store_matrix_sync(dst, C[mi][ni], 2 * H_, wmma::mem_row_major);
        }
}

// ---- fence-free scoped barrier ----------------------------------------------
__device__ __forceinline__ void group_sync(int gr, int step)
{
    __syncthreads();
    if (threadIdx.x == 0) {
        unsigned* arr = &g_arr[gr * 64];
        unsigned* gen = &g_gen[gr * 64];
        unsigned old;
        asm volatile("atom.acq_rel.gpu.global.add.u32 %0, [%1], 1;"
                     : "=r"(old) : "l"(arr) : "memory");
        if (old == (unsigned)(step * CPG + CPG - 1)) {
            asm volatile("st.release.gpu.global.u32 [%0], %1;"
                         :: "l"(gen), "r"((unsigned)(step + 1)) : "memory");
        } else {
            unsigned cur;
            do { asm volatile("ld.acquire.gpu.global.u32 %0, [%1];"
                              : "=r"(cur) : "l"(gen) : "memory");
            } while (cur <= (unsigned)step);
        }
    }
    __syncthreads();
}

// ---- persistent wmma recurrent kernel (R12 structure, overlap schedule) -----
// 128 CTAs = 2 groups x 64. CTA: 16 g-cols x 2 gates x 32 b.
// 8 warps k-split-8; warp tile m32 x n32, 3 mma terms, ring-3.
__global__ __launch_bounds__(TPB, 1) void rhn_wmma_kernel(
    const float* __restrict__ rh_b, const float* __restrict__ rt_b,
    float* __restrict__ out)
{
    extern __shared__ __half smh[];
    float* pr = (float*)smh + PART_F;
    const uint32_t sb = (uint32_t)__cvta_generic_to_shared(smh);

    const int tid  = threadIdx.x;
    const int wk   = tid >> 5;                 // k-split 0..7
    const int gb   = blockIdx.x;
    const int gr   = gb >> 6;                  // group 0..1
    const int c64  = gb & 63;
    const int bbase = gr * BPG;                // 32 b rows
    const int gbase = c64 * 16;                // 16 g-cols

    auto issue_w = [&](int l, int kt, int slot) {   // rows 0-63: 4 cp16/thread
        #pragma unroll
        for (int i = 0; i < 4; i++) {
            const int idx = i * 256 + tid;
            const int row = idx >> 4;          // 0..63
            const int seg = idx & 15;
            const int plane = row >> 5;
            const int rr = row & 31;
            const int gate = rr >> 4;
            const int g = gbase + (rr & 15);
            const __half* src = g_w16[gate][plane] + (size_t)l * H_ * H_
                                + (size_t)g * H_ + kt * 128 + seg * 8;
            cp16(sb + (uint32_t)(slot * SLOT_H + row * WPITCH + seg * 8) * 2, src);
        }
    };
    auto issue_s = [&](int pin, int kt, int slot) { // rows 64-127: 4 cp16/thread
        #pragma unroll
        for (int i = 0; i < 4; i++) {
            const int idx = i * 256 + tid;
            const int row = idx >> 4;          // 0..63
            const int seg = idx & 15;
            const int plane = row >> 5;
            const int b = bbase + (row & 31);
            const __half* src = g_s16[pin][plane] + (size_t)b * H_ + kt * 128 + seg * 8;
            cp16(sb + (uint32_t)(slot * SLOT_H + (64 + row) * WPITCH + seg * 8) * 2, src);
        }
    };

    // prologue: 4 groups W0, W1, S0, S1 (matches steady-state schedule)
    issue_w(0, 0, 0); CP_COMMIT();
    issue_w(0, 1, 1); CP_COMMIT();
    issue_s(0, 0, 0); CP_COMMIT();
    issue_s(0, 1, 1); CP_COMMIT();

    int t = 0, l = 0;
    for (int step = 0; step < T_ * L_; step++) {
        const int pin = step & 1;

        // hoisted epilogue operands: thread -> 2 (g,b) pairs
        const int i0 = tid * 2, i1 = tid * 2 + 1;
        const int gl0 = i0 & 15, bq0 = i0 >> 4;
        const int gl1 = i1 & 15, bq1 = i1 >> 4;
        const int g0 = gbase + gl0, g1 = gbase + gl1;
        const int b0g = bbase + bq0, b1g = bbase + bq1;
        const float bh0 = rh_b[l * H_ + g0], bt0 = rt_b[l * H_ + g0];
        const float bh1 = rh_b[l * H_ + g1], bt1 = rt_b[l * H_ + g1];
        const float* scur = g_state[pin];
        float*       snxt = g_state[pin ^ 1];
        const float so0 = __ldcg(&scur[(size_t)b0g * H_ + g0]);
        const float so1 = __ldcg(&scur[(size_t)b1g * H_ + g1]);
        float xh0 = 0.f, xt0 = 0.f, xh1 = 0.f, xt1 = 0.f;
        if (l == 0) {
            const float* xw0 = g_xw + (size_t)(t * B_ + b0g) * (2 * H_);
            const float* xw1 = g_xw + (size_t)(t * B_ + b1g) * (2 * H_);
            xh0 = xw0[g0]; xt0 = xw0[H_ + g0];
            xh1 = xw1[g1]; xt1 = xw1[H_ + g1];
        }

        wmma::fragment<wmma::accumulator, 16, 16, 16, float> C[2][2];
        #pragma unroll
        for (int mi = 0; mi < 2; mi++) {
            wmma::fill_fragment(C[mi][0], 0.0f);
            wmma::fill_fragment(C[mi][1], 0.0f);
        }

        const int koff = wk * 16;
        for (int kt = 0; kt < 8; kt++) {
            if (kt < 7) { CP_WAIT1(); } else { CP_WAIT0(); }
            __syncthreads();
            if (kt < 6) { issue_w(l, kt + 2, (kt + 2) % 3); issue_s(pin, kt + 2, (kt + 2) % 3); CP_COMMIT(); }

            const __half* slot = smh + (kt % 3) * SLOT_H;
            wmma::fragment<wmma::matrix_b, 16, 16, 16, __half, wmma::col_major> bh[2], bl[2];
            #pragma unroll
            for (int ni = 0; ni < 2; ni++) {
                wmma::load_matrix_sync(bh[ni], slot + (64 + ni * 16) * WPITCH + koff, WPITCH);
                wmma::load_matrix_sync(bl[ni], slot + (96 + ni * 16) * WPITCH + koff, WPITCH);
            }
            #pragma unroll
            for (int mi = 0; mi < 2; mi++) {
                wmma::fragment<wmma::matrix_a, 16, 16, 16, __half, wmma::row_major> ah, al;
                wmma::load_matrix_sync(ah, slot + (mi * 16) * WPITCH + koff, WPITCH);
                wmma::load_matrix_sync(al, slot + (32 + mi * 16) * WPITCH + koff, WPITCH);
                #pragma unroll
                for (int ni = 0; ni < 2; ni++) {
                    wmma::mma_sync(C[mi][ni], ah, bh[ni], C[mi][ni]);
                    wmma::mma_sync(C[mi][ni], ah, bl[ni], C[mi][ni]);
                    wmma::mma_sync(C[mi][ni], al, bh[ni], C[mi][ni]);
                }
            }
        }

        // partials: pr[wk][m 0..31][n 0..31]
        {
            float* base = pr + (size_t)wk * 32 * PRP;
            #pragma unroll
            for (int mi = 0; mi < 2; mi++)
                #pragma unroll
                for (int ni = 0; ni < 2; ni++)
                    wmma::store_matrix_sync(base + mi * 16 * PRP + ni * 16,
                                            C[mi][ni], PRP, wmma::mem_row_major);
        }
        __syncthreads();

        // advance + pre-issue BOTH next weight tiles (slots 0,1 free; read-only)
        int tn = t, ln = l + 1;
        if (ln == L_) { ln = 0; tn = t + 1; }
        const bool last = (step == T_ * L_ - 1);
        if (!last) {
            issue_w(ln, 0, 0); CP_COMMIT();     // overlaps epilogue + barrier
            issue_w(ln, 1, 1); CP_COMMIT();
        }

        // reduce + fused epilogue (2 outputs/thread)
        {
            float ph0 = bh0 + xh0, pt0 = bt0 + xt0;
            float ph1 = bh1 + xh1, pt1 = bt1 + xt1;
            #pragma unroll
            for (int w = 0; w < 8; w++) {
                const float* bk_ = pr + (size_t)w * 32 * PRP;
                ph0 += bk_[gl0 * PRP + bq0];
                pt0 += bk_[(16 + gl0) * PRP + bq0];
                ph1 += bk_[gl1 * PRP + bq1];
                pt1 += bk_[(16 + gl1) * PRP + bq1];
            }
            const float hh0 = tanhf(ph0), hh1 = tanhf(ph1);
            const float tg0 = 1.0f / (1.0f + expf(-pt0));
            const float tg1 = 1.0f / (1.0f + expf(-pt1));
            const float sn0 = fmaf(hh0 - so0, tg0, so0);
            const float sn1 = fmaf(hh1 - so1, tg1, so1);
            __stcg(&snxt[(size_t)b0g * H_ + g0], sn0);
            __stcg(&snxt[(size_t)b1g * H_ + g1], sn1);
            const __half a0 = __float2half_rn(sn0);
            const __half a1 = __float2half_rn(sn1);
            const __half c0 = __float2half_rn(sn0 - __half2float(a0));
            const __half c1 = __float2half_rn(sn1 - __half2float(a1));
            const size_t si0 = (size_t)b0g * H_ + g0;
            const size_t si1 = (size_t)b1g * H_ + g1;
            unsigned short u;
            u = __half_as_ushort(a0);
            asm volatile("st.global.cg.u16 [%0], %1;" :: "l"(&g_s16[pin ^ 1][0][si0]), "h"(u));
            u = __half_as_ushort(c0);
            asm volatile("st.global.cg.u16 [%0], %1;" :: "l"(&g_s16[pin ^ 1][1][si0]), "h"(u));
            u = __half_as_ushort(a1);
            asm volatile("st.global.cg.u16 [%0], %1;" :: "l"(&g_s16[pin ^ 1][0][si1]), "h"(u));
            u = __half_as_ushort(c1);
            asm volatile("st.global.cg.u16 [%0], %1;" :: "l"(&g_s16[pin ^ 1][1][si1]), "h"(u));
            if (l == L_ - 1) {
                out[((size_t)b0g * T_ + t) * H_ + g0] = sn0;
                out[((size_t)b1g * T_ + t) * H_ + g1] = sn1;
                if (t == T_ - 1) {
                    out[(size_t)B_ * T_ * H_ + (size_t)b0g * H_ + g0] = sn0;
                    out[(size_t)B_ * T_ * H_ + (size_t)b1g * H_ + g1] = sn1;
                }
            }
        }

        if (!last) {
            group_sync(gr, step);
            issue_s(pin ^ 1, 0, 0); CP_COMMIT();   // true dependency: state only
            issue_s(pin ^ 1, 1, 1); CP_COMMIT();
        }
        t = tn; l = ln;
    }
}

// ---------------------------------------------------------------------------
extern "C" void kernel_launch(void* const* d_in, const int* in_sizes, int n_in,
                              void* d_out, int out_size)
{
    const float* input = (const float*)d_in[0];
    const float* s0    = (const float*)d_in[1];
    const float* w_h   = (const float*)d_in[2];
    const float* w_t   = (const float*)d_in[3];
    const float* rh_w  = (const float*)d_in[4];
    const float* rh_b  = (const float*)d_in[5];
    const float* rt_w  = (const float*)d_in[6];
    const float* rt_b  = (const float*)d_in[7];
    float* out = (float*)d_out;

    static bool attr_set = false;
    if (!attr_set) {
        cudaFuncSetAttribute(rhn_wmma_kernel,
                             cudaFuncAttributeMaxDynamicSharedMemorySize, SMEM_BYTES);
        attr_set = true;
    }

    reset_barrier_kernel<<<1, 256>>>();
    cudaMemcpyToSymbolAsync(g_state, s0, (size_t)B_ * H_ * sizeof(float), 0,
                            cudaMemcpyDeviceToDevice);
    sinit_kernel<<<(B_ * H_ + 255) / 256, 256>>>(s0);
    wconvert_kernel<<<2048, 256>>>(rh_w, rt_w);
    iwconvert_kernel<<<1024, 256>>>(w_h, w_t);
    xconvert_kernel<<<4096, 256>>>(input);
    {
        dim3 grid(16, 256);
        xw_wmma_kernel<<<grid, 256>>>();
    }
    rhn_wmma_kernel<<<NC, TPB, SMEM_BYTES>>>(rh_b, rt_b, out);
}